// round 5
// baseline (speedup 1.0000x reference)
#include <cuda_runtime.h>
#include <cuda_bf16.h>
#include <cstdint>
#include <cstddef>

// Problem dims (fixed)
#define HD 1024
#define FD 3584
#define NE 8
#define RD 79
#define RP 96           // padded low-rank dim
#define KD 3680         // FD + RP (down-proj concat K)
#define TMAX 8192
#define AMAX (TMAX*2)

// ----------------------------------------------------------------------------
// Scratch (device globals — sanctioned scratch mechanism)
// ----------------------------------------------------------------------------
__device__ __align__(16) __nv_bfloat16 g_Xh[(size_t)TMAX * HD];
__device__ __align__(16) __nv_bfloat16 g_Xl[(size_t)TMAX * HD];
__device__ __align__(16) __nv_bfloat16 g_W1h[(size_t)NE * FD * HD];
__device__ __align__(16) __nv_bfloat16 g_W1l[(size_t)NE * FD * HD];
__device__ __align__(16) __nv_bfloat16 g_W3h[(size_t)NE * FD * HD];
__device__ __align__(16) __nv_bfloat16 g_W3l[(size_t)NE * FD * HD];
__device__ __align__(16) __nv_bfloat16 g_W2h[(size_t)NE * HD * KD];  // [W2|U2|0] concat
__device__ __align__(16) __nv_bfloat16 g_W2l[(size_t)NE * HD * KD];
__device__ __align__(16) __nv_bfloat16 g_V1h[(size_t)NE * RD * HD];
__device__ __align__(16) __nv_bfloat16 g_V1l[(size_t)NE * RD * HD];
__device__ __align__(16) __nv_bfloat16 g_V3h[(size_t)NE * RD * HD];
__device__ __align__(16) __nv_bfloat16 g_V3l[(size_t)NE * RD * HD];
__device__ __align__(16) __nv_bfloat16 g_V2h[(size_t)NE * RD * FD];
__device__ __align__(16) __nv_bfloat16 g_V2l[(size_t)NE * RD * FD];
__device__ __align__(16) __nv_bfloat16 g_U1h[(size_t)NE * FD * RP];  // zero-padded cols 79..95
__device__ __align__(16) __nv_bfloat16 g_U1l[(size_t)NE * FD * RP];
__device__ __align__(16) __nv_bfloat16 g_U3h[(size_t)NE * FD * RP];
__device__ __align__(16) __nv_bfloat16 g_U3l[(size_t)NE * FD * RP];
__device__ __align__(16) __nv_bfloat16 g_P1h[(size_t)AMAX * RP];
__device__ __align__(16) __nv_bfloat16 g_P1l[(size_t)AMAX * RP];
__device__ __align__(16) __nv_bfloat16 g_P3h[(size_t)AMAX * RP];
__device__ __align__(16) __nv_bfloat16 g_P3l[(size_t)AMAX * RP];
__device__ __align__(16) float g_gate[(size_t)AMAX * FD];
__device__ __align__(16) float g_up[(size_t)AMAX * FD];
__device__ __align__(16) __nv_bfloat16 g_Hh[(size_t)AMAX * KD];      // [Hact|Q2] planes
__device__ __align__(16) __nv_bfloat16 g_Hl[(size_t)AMAX * KD];

__device__ int   g_counts[NE];
__device__ int   g_offsets[NE + 1];
__device__ int   g_cursor[NE];
__device__ int   g_tok[AMAX];
__device__ float g_w[AMAX];
__device__ int   g_sel[TMAX * 2];
__device__ float g_wt[TMAX * 2];

// ----------------------------------------------------------------------------
// helpers
// ----------------------------------------------------------------------------
__device__ __forceinline__ void bsplit(float v, __nv_bfloat16& h, __nv_bfloat16& l) {
    h = __float2bfloat16(v);
    l = __float2bfloat16(v - __bfloat162float(h));
}
__device__ __forceinline__ uint32_t bpack(__nv_bfloat16 a, __nv_bfloat16 b) {
    return ((uint32_t)__bfloat16_as_ushort(b) << 16) | (uint32_t)__bfloat16_as_ushort(a);
}
__device__ __forceinline__ uint32_t smem_u32(const void* p) {
    uint32_t a;
    asm("{ .reg .u64 t; cvta.to.shared.u64 t, %1; cvt.u32.u64 %0, t; }" : "=r"(a) : "l"(p));
    return a;
}
__device__ __forceinline__ void cp_async16(uint32_t dst, const void* src) {
    asm volatile("cp.async.cg.shared.global [%0], [%1], 16;\n" :: "r"(dst), "l"(src));
}
#define CP_COMMIT() asm volatile("cp.async.commit_group;\n" ::: "memory")

__device__ __forceinline__ void mma_bf16(float* c, const uint32_t* a, const uint32_t* b) {
    asm volatile(
        "mma.sync.aligned.m16n8k16.row.col.f32.bf16.bf16.f32 "
        "{%0,%1,%2,%3}, {%4,%5,%6,%7}, {%8,%9}, {%0,%1,%2,%3};\n"
        : "+f"(c[0]), "+f"(c[1]), "+f"(c[2]), "+f"(c[3])
        : "r"(a[0]), "r"(a[1]), "r"(a[2]), "r"(a[3]), "r"(b[0]), "r"(b[1]));
}

// ----------------------------------------------------------------------------
// small kernels
// ----------------------------------------------------------------------------
__global__ void zero_kernel(float* __restrict__ out, size_t n) {
    size_t i = (size_t)blockIdx.x * blockDim.x + threadIdx.x;
    size_t stride = (size_t)gridDim.x * blockDim.x;
    for (; i < n; i += stride) out[i] = 0.0f;
    if (blockIdx.x == 0 && threadIdx.x < NE) {
        g_counts[threadIdx.x] = 0;
        g_cursor[threadIdx.x] = 0;
    }
}

// fp32 -> (hi, lo) bf16 planes, 2 elems/thread
__global__ void split2_kernel(const float2* __restrict__ src,
                              uint32_t* __restrict__ dh, uint32_t* __restrict__ dl, size_t n2) {
    size_t i = (size_t)blockIdx.x * blockDim.x + threadIdx.x;
    size_t stride = (size_t)gridDim.x * blockDim.x;
    for (; i < n2; i += stride) {
        float2 v = src[i];
        __nv_bfloat16 h0, l0, h1, l1;
        bsplit(v.x, h0, l0);
        bsplit(v.y, h1, l1);
        dh[i] = bpack(h0, h1);
        dl[i] = bpack(l0, l1);
    }
}

// U (rows x 79) -> planes (rows x 96), zero-padded
__global__ void splitpad_kernel(const float* __restrict__ src,
                                uint32_t* __restrict__ dh, uint32_t* __restrict__ dl, int rows) {
    long i = (long)blockIdx.x * blockDim.x + threadIdx.x;
    long total = (long)rows * (RP / 2);
    long stride = (long)gridDim.x * blockDim.x;
    for (; i < total; i += stride) {
        int r = (int)(i / (RP / 2)), j = (int)(i % (RP / 2));
        int c0 = 2 * j, c1 = 2 * j + 1;
        float v0 = (c0 < RD) ? src[(long)r * RD + c0] : 0.0f;
        float v1 = (c1 < RD) ? src[(long)r * RD + c1] : 0.0f;
        __nv_bfloat16 h0, l0, h1, l1;
        bsplit(v0, h0, l0);
        bsplit(v1, h1, l1);
        dh[i] = bpack(h0, h1);
        dl[i] = bpack(l0, l1);
    }
}

// [W2 | U2 | 0] concat planes: rows = NE*HD, row k-width KD
__global__ void w2cat_kernel(const float* __restrict__ W2, const float* __restrict__ U2,
                             uint32_t* __restrict__ dh, uint32_t* __restrict__ dl) {
    long i = (long)blockIdx.x * blockDim.x + threadIdx.x;
    long total = (long)NE * HD * (KD / 2);
    long stride = (long)gridDim.x * blockDim.x;
    for (; i < total; i += stride) {
        long row = i / (KD / 2);
        int j = (int)(i % (KD / 2));
        int c0 = 2 * j, c1 = 2 * j + 1;
        const float* wrow = W2 + row * FD;
        const float* urow = U2 + row * RD;
        float v0 = (c0 < FD) ? wrow[c0] : ((c0 - FD < RD) ? urow[c0 - FD] : 0.0f);
        float v1 = (c1 < FD) ? wrow[c1] : ((c1 - FD < RD) ? urow[c1 - FD] : 0.0f);
        __nv_bfloat16 h0, l0, h1, l1;
        bsplit(v0, h0, l0);
        bsplit(v1, h1, l1);
        dh[i] = bpack(h0, h1);
        dl[i] = bpack(l0, l1);
    }
}

__global__ void router_kernel(const float* __restrict__ x,
                              const float* __restrict__ gw,
                              float* __restrict__ logits_out) {
    int t = blockIdx.x;
    __shared__ float xs[HD];
    __shared__ float lg[NE];
    int tid = threadIdx.x;
    for (int i = tid; i < HD; i += 256) xs[i] = x[(size_t)t * HD + i];
    __syncthreads();
    int w = tid >> 5, lane = tid & 31;
    if (w < NE) {
        const float* grow = gw + (size_t)w * HD;
        float s = 0.0f;
        for (int k = lane; k < HD; k += 32) s += xs[k] * grow[k];
        #pragma unroll
        for (int o = 16; o > 0; o >>= 1) s += __shfl_xor_sync(0xffffffffu, s, o);
        if (lane == 0) lg[w] = s;
    }
    __syncthreads();
    if (tid == 0) {
        float l[NE], m = -1e30f;
        #pragma unroll
        for (int e = 0; e < NE; e++) {
            l[e] = lg[e];
            logits_out[(size_t)t * NE + e] = l[e];
            if (l[e] > m) m = l[e];
        }
        float p[NE];
        #pragma unroll
        for (int e = 0; e < NE; e++) p[e] = expf(l[e] - m);
        int i0 = 0;
        #pragma unroll
        for (int e = 1; e < NE; e++) if (p[e] > p[i0]) i0 = e;
        int i1 = (i0 == 0) ? 1 : 0;
        #pragma unroll
        for (int e = 0; e < NE; e++) {
            if (e == i0) continue;
            if (p[e] > p[i1]) i1 = e;
        }
        float p0 = p[i0], p1 = p[i1];
        float inv = 1.0f / (p0 + p1);
        g_sel[t * 2 + 0] = i0;  g_wt[t * 2 + 0] = p0 * inv;
        g_sel[t * 2 + 1] = i1;  g_wt[t * 2 + 1] = p1 * inv;
        atomicAdd(&g_counts[i0], 1);
        atomicAdd(&g_counts[i1], 1);
    }
}

__global__ void scan_kernel() {
    int off = 0;
    g_offsets[0] = 0;
    for (int e = 0; e < NE; e++) {
        off += g_counts[e];
        g_offsets[e + 1] = off;
        g_cursor[e] = g_offsets[e];
    }
}

__global__ void scatter_kernel(int T) {
    int t = blockIdx.x * blockDim.x + threadIdx.x;
    if (t >= T) return;
    #pragma unroll
    for (int j = 0; j < 2; j++) {
        int e = g_sel[t * 2 + j];
        int slot = atomicAdd(&g_cursor[e], 1);
        g_tok[slot] = t;
        g_w[slot] = g_wt[t * 2 + j];
    }
}

// Hact = silu(gate)*up -> bf16 planes into [A x KD] buffer cols 0..FD-1
__global__ void silu_split_kernel(const float2* __restrict__ g, const float2* __restrict__ u,
                                  uint32_t* __restrict__ hh, uint32_t* __restrict__ hl, int Arows) {
    long i = (long)blockIdx.x * blockDim.x + threadIdx.x;
    long total = (long)Arows * (FD / 2);
    long stride = (long)gridDim.x * blockDim.x;
    for (; i < total; i += stride) {
        long m = i / (FD / 2);
        int j = (int)(i % (FD / 2));
        float2 gv = g[m * (FD / 2) + j];
        float2 uv = u[m * (FD / 2) + j];
        float a0 = gv.x / (1.0f + expf(-gv.x)) * uv.x;
        float a1 = gv.y / (1.0f + expf(-gv.y)) * uv.y;
        __nv_bfloat16 h0, l0, h1, l1;
        bsplit(a0, h0, l0);
        bsplit(a1, h1, l1);
        long o = m * (KD / 2) + j;
        hh[o] = bpack(h0, h1);
        hl[o] = bpack(l0, l1);
    }
}

// ----------------------------------------------------------------------------
// Split-bf16 tensor-core MoE GEMM (3-term: AhBh + AhBl + AlBh), cp.async 4-stage.
//   C[m,n] = sum_{k<K1} A(row_m)[k] * B(e)[n,k]
//   smem row: [hi 64B][lo 64B][pad 16B] = 144B  (conflict-free STS & LDS)
//   EPI 0: fp32 store   EPI 1: bf16 hi/lo plane store
//   EPI 2: fp32 +=      EPI 3: atomicAdd(out[tok*HD+n], w*acc)
// ----------------------------------------------------------------------------
template <int BM, int BN, int WARPS_M, int WARPS_N, int K1, int ASTR, bool GATHER, int EPI>
__global__ __launch_bounds__(256)
void gemm_bf(const __nv_bfloat16* __restrict__ Ahb, const __nv_bfloat16* __restrict__ Alb,
             const __nv_bfloat16* __restrict__ Bhb, const __nv_bfloat16* __restrict__ Blb,
             size_t bstride, int nbrows,
             float* __restrict__ Cf, int ldc,
             __nv_bfloat16* __restrict__ Ch, __nv_bfloat16* __restrict__ Cl, int ostr,
             float* __restrict__ outp) {
    constexpr int BK = 32;
    constexpr int S = 4;                       // pipeline stages (power of 2)
    constexpr int NKT = K1 / BK;
    constexpr int WM = BM / WARPS_M;
    constexpr int WN = BN / WARPS_N;
    constexpr int MT = WM / 16;
    constexpr int NTL = WN / 8;
    constexpr int ROWB = 144;                  // 128B data + 16B pad
    constexpr int SB = (BM + BN) * ROWB;       // bytes per stage
    constexpr int LA = BM * 8 / 256;           // 16B chunks/thread (A)
    constexpr int LB = BN * 8 / 256;
    static_assert(BM * 8 % 256 == 0 && BN * 8 % 256 == 0, "tiles");

    const int e = blockIdx.z;
    const int base = g_offsets[e];
    const int cnt = g_offsets[e + 1] - base;
    const int m0 = blockIdx.y * BM;
    if (m0 >= cnt) return;
    const int n0 = blockIdx.x * BN;

    extern __shared__ char sm[];
    const uint32_t sbase = smem_u32(sm);

    const int tid = threadIdx.x;
    const int lane = tid & 31;
    const int wid = tid >> 5;
    const int wm = wid % WARPS_M;
    const int wn = wid / WARPS_M;

    // ---- cp.async chunk metadata ----
    const __nv_bfloat16* asrc[LA];
    uint32_t adst[LA];
    #pragma unroll
    for (int i = 0; i < LA; i++) {
        int idx = tid + i * 256;
        int row = idx >> 3, sub = idx & 7;
        int pl = sub >> 2, q = sub & 3;
        adst[i] = sbase + (uint32_t)(row * ROWB + pl * 64 + q * 16);
        int m = m0 + row;
        int ga = base + ((m < cnt) ? m : (cnt - 1));
        long grow = GATHER ? (long)g_tok[ga] : (long)ga;
        asrc[i] = (pl ? Alb : Ahb) + grow * ASTR + q * 8;
    }
    const __nv_bfloat16* bsrc[LB];
    uint32_t bdst[LB];
    #pragma unroll
    for (int i = 0; i < LB; i++) {
        int idx = tid + i * 256;
        int row = idx >> 3, sub = idx & 7;
        int pl = sub >> 2, q = sub & 3;
        bdst[i] = sbase + (uint32_t)(BM * ROWB + row * ROWB + pl * 64 + q * 16);
        int n = n0 + row;
        int nn = (n < nbrows) ? n : 0;
        bsrc[i] = (pl ? Blb : Bhb) + (size_t)e * bstride + (size_t)nn * K1 + q * 8;
    }

    auto issue = [&](int c) {
        const int kb = c * BK;
        const uint32_t so = (uint32_t)((c & (S - 1)) * SB);
        #pragma unroll
        for (int i = 0; i < LA; i++) cp_async16(adst[i] + so, asrc[i] + kb);
        #pragma unroll
        for (int i = 0; i < LB; i++) cp_async16(bdst[i] + so, bsrc[i] + kb);
    };

    float acc[MT][NTL][4];
    #pragma unroll
    for (int mt = 0; mt < MT; mt++)
        #pragma unroll
        for (int nt = 0; nt < NTL; nt++)
            #pragma unroll
            for (int j = 0; j < 4; j++) acc[mt][nt][j] = 0.f;

    // prologue: stages 0..S-2 (skip beyond NKT, still commit)
    #pragma unroll
    for (int s = 0; s < S - 1; s++) {
        if (s < NKT) issue(s);
        CP_COMMIT();
    }

    for (int c = 0; c < NKT; c++) {
        asm volatile("cp.async.wait_group %0;\n" :: "n"(S - 2) : "memory");
        __syncthreads();                         // stage c published; compute(c-1) done
        if (c + S - 1 < NKT) issue(c + S - 1);   // overwrites stage (c-1)%S — safe
        CP_COMMIT();

        const char* As = sm + (c & (S - 1)) * SB;
        const char* Bs = As + BM * ROWB;
        #pragma unroll
        for (int ks = 0; ks < 2; ks++) {
            const int ko = ks * 32 + (lane & 3) * 4;
            uint32_t ah[MT][4], al[MT][4], bh[NTL][2], bl[NTL][2];
            #pragma unroll
            for (int mt = 0; mt < MT; mt++) {
                const char* p = As + (wm * WM + mt * 16 + (lane >> 2)) * ROWB;
                ah[mt][0] = *(const uint32_t*)(p + ko);
                ah[mt][1] = *(const uint32_t*)(p + 8 * ROWB + ko);
                ah[mt][2] = *(const uint32_t*)(p + ko + 16);
                ah[mt][3] = *(const uint32_t*)(p + 8 * ROWB + ko + 16);
                al[mt][0] = *(const uint32_t*)(p + 64 + ko);
                al[mt][1] = *(const uint32_t*)(p + 8 * ROWB + 64 + ko);
                al[mt][2] = *(const uint32_t*)(p + 64 + ko + 16);
                al[mt][3] = *(const uint32_t*)(p + 8 * ROWB + 64 + ko + 16);
            }
            #pragma unroll
            for (int nt = 0; nt < NTL; nt++) {
                const char* p = Bs + (wn * WN + nt * 8 + (lane >> 2)) * ROWB;
                bh[nt][0] = *(const uint32_t*)(p + ko);
                bh[nt][1] = *(const uint32_t*)(p + ko + 16);
                bl[nt][0] = *(const uint32_t*)(p + 64 + ko);
                bl[nt][1] = *(const uint32_t*)(p + 64 + ko + 16);
            }
            #pragma unroll
            for (int mt = 0; mt < MT; mt++)
                #pragma unroll
                for (int nt = 0; nt < NTL; nt++) {
                    mma_bf16(acc[mt][nt], ah[mt], bh[nt]);   // hi*hi
                    mma_bf16(acc[mt][nt], ah[mt], bl[nt]);   // hi*lo
                    mma_bf16(acc[mt][nt], al[mt], bh[nt]);   // lo*hi
                }
        }
    }

    // ---- epilogue ----
    #pragma unroll
    for (int mt = 0; mt < MT; mt++) {
        #pragma unroll
        for (int h = 0; h < 2; h++) {
            int ml = wm * WM + mt * 16 + (lane >> 2) + h * 8;
            int m = m0 + ml;
            if (m >= cnt) continue;
            int ga = base + m;
            #pragma unroll
            for (int nt = 0; nt < NTL; nt++) {
                int col = n0 + wn * WN + nt * 8 + 2 * (lane & 3);
                float v0 = acc[mt][nt][h * 2 + 0];
                float v1 = acc[mt][nt][h * 2 + 1];
                if (EPI == 0) {
                    float2 v = make_float2(v0, v1);
                    *reinterpret_cast<float2*>(Cf + (size_t)ga * ldc + col) = v;
                } else if (EPI == 1) {
                    __nv_bfloat16 h0, l0, h1, l1;
                    bsplit(v0, h0, l0);
                    bsplit(v1, h1, l1);
                    *reinterpret_cast<uint32_t*>(Ch + (size_t)ga * ostr + col) = bpack(h0, h1);
                    *reinterpret_cast<uint32_t*>(Cl + (size_t)ga * ostr + col) = bpack(l0, l1);
                } else if (EPI == 2) {
                    float2* cp2 = reinterpret_cast<float2*>(Cf + (size_t)ga * ldc + col);
                    float2 v = *cp2;
                    v.x += v0; v.y += v1;
                    *cp2 = v;
                } else {
                    int tok = g_tok[ga];
                    float wgt = g_w[ga];
                    float* orow = outp + (size_t)tok * HD;
                    atomicAdd(&orow[col], wgt * v0);
                    atomicAdd(&orow[col + 1], wgt * v1);
                }
            }
        }
    }
}

// ----------------------------------------------------------------------------
// kernel_launch
// Inputs: hidden_states, gate_w, W1, W2, W3, U1, V1, U2, V2, U3, V3
// Output: [out (T*H f32)] then [router_logits (T*E f32)]
// ----------------------------------------------------------------------------
extern "C" void kernel_launch(void* const* d_in, const int* in_sizes, int n_in,
                              void* d_out, int out_size) {
    const float* x  = (const float*)d_in[0];
    const float* gw = (const float*)d_in[1];
    const float* W1 = (const float*)d_in[2];
    const float* W2 = (const float*)d_in[3];
    const float* W3 = (const float*)d_in[4];
    const float* U1 = (const float*)d_in[5];
    const float* V1 = (const float*)d_in[6];
    const float* U2 = (const float*)d_in[7];
    const float* V2 = (const float*)d_in[8];
    const float* U3 = (const float*)d_in[9];
    const float* V3 = (const float*)d_in[10];
    (void)n_in; (void)out_size;

    const int T = in_sizes[0] / HD;
    const int A = T * 2;

    float* out    = (float*)d_out;
    float* logits = out + (size_t)T * HD;

    // GEMM instantiations
    auto* gP  = gemm_bf<128,  96, 4, 2, HD, HD,  true,  1>;  // P = X@V^T  -> bf16 planes
    auto* gM  = gemm_bf<128, 128, 2, 4, HD, HD,  true,  0>;  // gate/up main -> fp32
    auto* gLR = gemm_bf<128, 128, 2, 4, RP, RP,  false, 2>;  // += P@U^T (fp32 RMW)
    auto* gQ  = gemm_bf<128,  96, 4, 2, FD, KD,  false, 1>;  // Q2 = H@V2^T -> planes into H cols 3584+
    auto* gD  = gemm_bf<128, 128, 2, 4, KD, KD,  false, 3>;  // down concat (atomic)
    const int SM128 = 4 * (128 + 128) * 144;   // 147456 B
    const int SM96  = 4 * (128 +  96) * 144;   // 129024 B
    cudaFuncSetAttribute((const void*)gP,  cudaFuncAttributeMaxDynamicSharedMemorySize, SM96);
    cudaFuncSetAttribute((const void*)gM,  cudaFuncAttributeMaxDynamicSharedMemorySize, SM128);
    cudaFuncSetAttribute((const void*)gLR, cudaFuncAttributeMaxDynamicSharedMemorySize, SM128);
    cudaFuncSetAttribute((const void*)gQ,  cudaFuncAttributeMaxDynamicSharedMemorySize, SM96);
    cudaFuncSetAttribute((const void*)gD,  cudaFuncAttributeMaxDynamicSharedMemorySize, SM128);

    zero_kernel<<<2048, 256>>>(out, (size_t)T * HD);
    router_kernel<<<T, 256>>>(x, gw, logits);
    scan_kernel<<<1, 1>>>();
    scatter_kernel<<<(T + 255) / 256, 256>>>(T);

    // split all GEMM operands into bf16 hi/lo planes
    split2_kernel<<<2048, 256>>>((const float2*)x,  (uint32_t*)g_Xh,  (uint32_t*)g_Xl,  (size_t)T * HD / 2);
    split2_kernel<<<4096, 256>>>((const float2*)W1, (uint32_t*)g_W1h, (uint32_t*)g_W1l, (size_t)NE * FD * HD / 2);
    split2_kernel<<<4096, 256>>>((const float2*)W3, (uint32_t*)g_W3h, (uint32_t*)g_W3l, (size_t)NE * FD * HD / 2);
    split2_kernel<<<1024, 256>>>((const float2*)V1, (uint32_t*)g_V1h, (uint32_t*)g_V1l, (size_t)NE * RD * HD / 2);
    split2_kernel<<<1024, 256>>>((const float2*)V3, (uint32_t*)g_V3h, (uint32_t*)g_V3l, (size_t)NE * RD * HD / 2);
    split2_kernel<<<2048, 256>>>((const float2*)V2, (uint32_t*)g_V2h, (uint32_t*)g_V2l, (size_t)NE * RD * FD / 2);
    splitpad_kernel<<<2048, 256>>>(U1, (uint32_t*)g_U1h, (uint32_t*)g_U1l, NE * FD);
    splitpad_kernel<<<2048, 256>>>(U3, (uint32_t*)g_U3h, (uint32_t*)g_U3l, NE * FD);
    w2cat_kernel<<<4096, 256>>>(W2, U2, (uint32_t*)g_W2h, (uint32_t*)g_W2l);

    const int mt128 = (T + 127) / 128;

    // P1 = X@V1^T, P3 = X@V3^T   (bf16-plane outputs, stride 96)
    {
        dim3 grid(1, mt128, NE);
        gP<<<grid, 256, SM96>>>(g_Xh, g_Xl, g_V1h, g_V1l, (size_t)RD * HD, RD,
                                nullptr, 0, g_P1h, g_P1l, RP, nullptr);
        gP<<<grid, 256, SM96>>>(g_Xh, g_Xl, g_V3h, g_V3l, (size_t)RD * HD, RD,
                                nullptr, 0, g_P3h, g_P3l, RP, nullptr);
    }
    // gate = X@W1^T, up = X@W3^T  (fp32)
    {
        dim3 grid(FD / 128, mt128, NE);
        gM<<<grid, 256, SM128>>>(g_Xh, g_Xl, g_W1h, g_W1l, (size_t)FD * HD, FD,
                                 g_gate, FD, nullptr, nullptr, 0, nullptr);
        gM<<<grid, 256, SM128>>>(g_Xh, g_Xl, g_W3h, g_W3l, (size_t)FD * HD, FD,
                                 g_up, FD, nullptr, nullptr, 0, nullptr);
    }
    // gate += P1@U1^T, up += P3@U3^T  (K=96; zero-padded U cols nullify P junk)
    {
        dim3 grid(FD / 128, mt128, NE);
        gLR<<<grid, 256, SM128>>>(g_P1h, g_P1l, g_U1h, g_U1l, (size_t)FD * RP, FD,
                                  g_gate, FD, nullptr, nullptr, 0, nullptr);
        gLR<<<grid, 256, SM128>>>(g_P3h, g_P3l, g_U3h, g_U3l, (size_t)FD * RP, FD,
                                  g_up, FD, nullptr, nullptr, 0, nullptr);
    }
    // Hact = silu(gate)*up -> bf16 planes (cols 0..FD-1 of [A x KD])
    silu_split_kernel<<<4096, 256>>>((const float2*)g_gate, (const float2*)g_up,
                                     (uint32_t*)g_Hh, (uint32_t*)g_Hl, A);

    // Q2 = H@V2^T -> planes written into H buffer cols FD..FD+95
    {
        dim3 grid(1, mt128, NE);
        gQ<<<grid, 256, SM96>>>(g_Hh, g_Hl, g_V2h, g_V2l, (size_t)RD * FD, RD,
                                nullptr, 0, g_Hh + FD, g_Hl + FD, KD, nullptr);
    }
    // out += w * ([H|Q2] @ [W2|U2]^T)   (K=3680, atomic scatter)
    {
        dim3 grid(HD / 128, mt128, NE);
        gD<<<grid, 256, SM128>>>(g_Hh, g_Hl, g_W2h, g_W2l, (size_t)HD * KD, HD,
                                 nullptr, 0, nullptr, nullptr, 0, out);
    }
}

// round 6
// speedup vs baseline: 4.9105x; 4.9105x over previous
#include <cuda_runtime.h>
#include <cstdint>
#include <cstddef>

// Problem dims (fixed)
#define HD 1024
#define FD 3584
#define NE 8
#define RD 79
#define RP 96        // padded low-rank dim (multiple of 16)
#define TMAX 8192
#define AMAX (TMAX*2)

// ----------------------------------------------------------------------------
// Scratch (device globals)
// ----------------------------------------------------------------------------
__device__ __align__(16) float g_P1[(size_t)AMAX * RP];
__device__ __align__(16) float g_P3[(size_t)AMAX * RP];
__device__ __align__(16) float g_Q2[(size_t)AMAX * RP];
__device__ __align__(16) float g_gate[(size_t)AMAX * FD];
__device__ __align__(16) float g_up[(size_t)AMAX * FD];
__device__ __align__(16) float g_U1p[(size_t)NE * FD * RP];
__device__ __align__(16) float g_U3p[(size_t)NE * FD * RP];
__device__ __align__(16) float g_U2p[(size_t)NE * HD * RP];

__device__ int   g_counts[NE];
__device__ int   g_offsets[NE + 1];
__device__ int   g_cursor[NE];
__device__ int   g_tok[AMAX];
__device__ float g_w[AMAX];
__device__ int   g_sel[TMAX * 2];
__device__ float g_wt[TMAX * 2];

// ----------------------------------------------------------------------------
// f32x2 helpers (packed dual-FMA; SASS FFMA2 — sm_100-family base feature)
// ----------------------------------------------------------------------------
__device__ __forceinline__ unsigned long long rep2(float x) {
    unsigned long long r;
    asm("mov.b64 %0, {%1, %1};" : "=l"(r) : "f"(x));
    return r;
}
__device__ __forceinline__ unsigned long long pk2(float x, float y) {
    unsigned long long r;
    asm("mov.b64 %0, {%1, %2};" : "=l"(r) : "f"(x), "f"(y));
    return r;
}
__device__ __forceinline__ void fma2(unsigned long long& c, unsigned long long a,
                                     unsigned long long b) {
    asm("fma.rn.f32x2 %0, %1, %2, %0;" : "+l"(c) : "l"(a), "l"(b));
}
__device__ __forceinline__ void upk2(unsigned long long v, float& x, float& y) {
    asm("mov.b64 {%0, %1}, %2;" : "=f"(x), "=f"(y) : "l"(v));
}

// ----------------------------------------------------------------------------
// small kernels
// ----------------------------------------------------------------------------
__global__ void zero_kernel(float* __restrict__ out, size_t n) {
    size_t i = (size_t)blockIdx.x * blockDim.x + threadIdx.x;
    size_t stride = (size_t)gridDim.x * blockDim.x;
    for (; i < n; i += stride) out[i] = 0.0f;
    if (blockIdx.x == 0 && threadIdx.x < NE) {
        g_counts[threadIdx.x] = 0;
        g_cursor[threadIdx.x] = 0;
    }
}

__global__ void router_kernel(const float* __restrict__ x,
                              const float* __restrict__ gw,
                              float* __restrict__ logits_out) {
    int t = blockIdx.x;
    __shared__ float xs[HD];
    __shared__ float lg[NE];
    int tid = threadIdx.x;
    for (int i = tid; i < HD; i += 256) xs[i] = x[(size_t)t * HD + i];
    __syncthreads();
    int w = tid >> 5, lane = tid & 31;
    if (w < NE) {
        const float* grow = gw + (size_t)w * HD;
        float s = 0.0f;
        for (int k = lane; k < HD; k += 32) s += xs[k] * grow[k];
        #pragma unroll
        for (int o = 16; o > 0; o >>= 1) s += __shfl_xor_sync(0xffffffffu, s, o);
        if (lane == 0) lg[w] = s;
    }
    __syncthreads();
    if (tid == 0) {
        float l[NE], m = -1e30f;
        #pragma unroll
        for (int e = 0; e < NE; e++) {
            l[e] = lg[e];
            logits_out[(size_t)t * NE + e] = l[e];
            if (l[e] > m) m = l[e];
        }
        float p[NE];
        #pragma unroll
        for (int e = 0; e < NE; e++) p[e] = expf(l[e] - m);
        int i0 = 0;
        #pragma unroll
        for (int e = 1; e < NE; e++) if (p[e] > p[i0]) i0 = e;
        int i1 = (i0 == 0) ? 1 : 0;
        #pragma unroll
        for (int e = 0; e < NE; e++) {
            if (e == i0) continue;
            if (p[e] > p[i1]) i1 = e;
        }
        float p0 = p[i0], p1 = p[i1];
        float inv = 1.0f / (p0 + p1);
        g_sel[t * 2 + 0] = i0;  g_wt[t * 2 + 0] = p0 * inv;
        g_sel[t * 2 + 1] = i1;  g_wt[t * 2 + 1] = p1 * inv;
        atomicAdd(&g_counts[i0], 1);
        atomicAdd(&g_counts[i1], 1);
    }
}

__global__ void scan_kernel() {
    int off = 0;
    g_offsets[0] = 0;
    for (int e = 0; e < NE; e++) {
        off += g_counts[e];
        g_offsets[e + 1] = off;
        g_cursor[e] = g_offsets[e];
    }
}

__global__ void scatter_kernel(int T) {
    int t = blockIdx.x * blockDim.x + threadIdx.x;
    if (t >= T) return;
    #pragma unroll
    for (int j = 0; j < 2; j++) {
        int e = g_sel[t * 2 + j];
        int slot = atomicAdd(&g_cursor[e], 1);
        g_tok[slot] = t;
        g_w[slot] = g_wt[t * 2 + j];
    }
}

// rows of RD -> rows of RP, zero-padded (fp32 exact)
__global__ void pad_kernel(const float* __restrict__ src, float* __restrict__ dst, int rows) {
    long i = (long)blockIdx.x * blockDim.x + threadIdx.x;
    long total = (long)rows * RP;
    long stride = (long)gridDim.x * blockDim.x;
    for (; i < total; i += stride) {
        int r = (int)(i / RP), c = (int)(i % RP);
        dst[i] = (c < RD) ? src[(long)r * RD + c] : 0.0f;
    }
}

__global__ void silu_mul_kernel(float* __restrict__ g, const float* __restrict__ u, size_t n) {
    size_t i = (size_t)blockIdx.x * blockDim.x + threadIdx.x;
    size_t stride = (size_t)gridDim.x * blockDim.x;
    for (; i < n; i += stride) {
        float gv = g[i];
        float s = 1.0f / (1.0f + expf(-gv));
        g[i] = gv * s * u[i];
    }
}

// ----------------------------------------------------------------------------
// FP32 MoE GEMM on the FFMA2 (fma.rn.f32x2) pipe.
//   C[m,n] = sum_{k<K1} A(row_m)[k] * B(e)[n,k]
//   Tile 128x128xBK16, 256 threads, 8x8 micro-tile as 32 dual-FMAs/thread/k.
//   Double-buffered smem + register-staged global loads.
//   EPI 0: crow[n] = (n<NReal ? acc : 0), for n<NPad
//   EPI 2: crow[n] += acc
//   EPI 3: atomicAdd(out[tok*HD+n], w[ga]*acc)
// ----------------------------------------------------------------------------
template <int K1, bool GATHER, int EPI>
__global__ __launch_bounds__(256)
void gemm_f2(const float* __restrict__ A1,
             const float* __restrict__ Bbase, size_t bstr, int nbrows,
             float* __restrict__ C, int ldc, int NReal, int NPad,
             float* __restrict__ outp) {
    constexpr int BK = 16;
    constexpr int NKT = K1 / BK;
    constexpr int LDA = 132;                  // padded row (floats)
    constexpr int HALFB = BK * LDA;           // 2112 floats: As part of one buffer
    constexpr int BUFSZ = 2 * HALFB;          // As + Bs per buffer

    __shared__ float sm[2 * BUFSZ];           // 33,792 B

    const int e = blockIdx.z;
    const int base = g_offsets[e];
    const int cnt = g_offsets[e + 1] - base;
    const int m0 = blockIdx.y * 128;
    if (m0 >= cnt) return;
    const int n0 = blockIdx.x * 128;

    const int tid = threadIdx.x;

    // ---- loader mapping: row = tid>>1, k-offset = (tid&1)*8, 2 float4 each ----
    const int lrow = tid >> 1;
    const int lk = (tid & 1) * 8;
    int am = m0 + lrow;
    int aga = base + ((am < cnt) ? am : (cnt - 1));
    long agrow = GATHER ? (long)g_tok[aga] : (long)aga;
    const float* aptr = A1 + agrow * K1 + lk;
    int bn = n0 + lrow;
    int bnn = (bn < nbrows) ? bn : 0;
    const float* bptr = Bbase + (size_t)e * bstr + (size_t)bnn * K1 + lk;

    float4 ra0, ra1, rb0, rb1;
    auto ldg = [&](int kt) {
        const int kb = kt * BK;
        ra0 = *reinterpret_cast<const float4*>(aptr + kb);
        ra1 = *reinterpret_cast<const float4*>(aptr + kb + 4);
        rb0 = *reinterpret_cast<const float4*>(bptr + kb);
        rb1 = *reinterpret_cast<const float4*>(bptr + kb + 4);
    };
    auto sts = [&](int buf) {
        float* As = sm + buf * BUFSZ;
        float* Bs = As + HALFB;
        As[(lk + 0) * LDA + lrow] = ra0.x;
        As[(lk + 1) * LDA + lrow] = ra0.y;
        As[(lk + 2) * LDA + lrow] = ra0.z;
        As[(lk + 3) * LDA + lrow] = ra0.w;
        As[(lk + 4) * LDA + lrow] = ra1.x;
        As[(lk + 5) * LDA + lrow] = ra1.y;
        As[(lk + 6) * LDA + lrow] = ra1.z;
        As[(lk + 7) * LDA + lrow] = ra1.w;
        Bs[(lk + 0) * LDA + lrow] = rb0.x;
        Bs[(lk + 1) * LDA + lrow] = rb0.y;
        Bs[(lk + 2) * LDA + lrow] = rb0.z;
        Bs[(lk + 3) * LDA + lrow] = rb0.w;
        Bs[(lk + 4) * LDA + lrow] = rb1.x;
        Bs[(lk + 5) * LDA + lrow] = rb1.y;
        Bs[(lk + 6) * LDA + lrow] = rb1.z;
        Bs[(lk + 7) * LDA + lrow] = rb1.w;
    };

    // ---- compute mapping ----
    const int ty4 = (tid >> 4) * 4;           // row chunk base (0..60)
    const int tx4 = (tid & 15) * 4;           // col chunk base (0..60)

    unsigned long long acc[2][2][4][2];
    #pragma unroll
    for (int mi = 0; mi < 2; mi++)
        #pragma unroll
        for (int ni = 0; ni < 2; ni++)
            #pragma unroll
            for (int i = 0; i < 4; i++) {
                acc[mi][ni][i][0] = 0ull;
                acc[mi][ni][i][1] = 0ull;
            }

    ldg(0);
    sts(0);
    __syncthreads();

    for (int kt = 0; kt < NKT; kt++) {
        if (kt + 1 < NKT) ldg(kt + 1);       // overlap with compute below
        const float* As = sm + (kt & 1) * BUFSZ;
        const float* Bs = As + HALFB;
        #pragma unroll
        for (int k = 0; k < BK; k++) {
            float4 av0 = *reinterpret_cast<const float4*>(As + k * LDA + ty4);
            float4 av1 = *reinterpret_cast<const float4*>(As + k * LDA + 64 + ty4);
            float4 bv0 = *reinterpret_cast<const float4*>(Bs + k * LDA + tx4);
            float4 bv1 = *reinterpret_cast<const float4*>(Bs + k * LDA + 64 + tx4);
            unsigned long long bp[2][2] = {
                {pk2(bv0.x, bv0.y), pk2(bv0.z, bv0.w)},
                {pk2(bv1.x, bv1.y), pk2(bv1.z, bv1.w)}};
            unsigned long long ar[2][4] = {
                {rep2(av0.x), rep2(av0.y), rep2(av0.z), rep2(av0.w)},
                {rep2(av1.x), rep2(av1.y), rep2(av1.z), rep2(av1.w)}};
            #pragma unroll
            for (int mi = 0; mi < 2; mi++)
                #pragma unroll
                for (int i = 0; i < 4; i++)
                    #pragma unroll
                    for (int ni = 0; ni < 2; ni++) {
                        fma2(acc[mi][ni][i][0], ar[mi][i], bp[ni][0]);
                        fma2(acc[mi][ni][i][1], ar[mi][i], bp[ni][1]);
                    }
        }
        if (kt + 1 < NKT) {
            __syncthreads();
            sts((kt + 1) & 1);
            __syncthreads();
        }
    }

    // ---- epilogue ----
    #pragma unroll
    for (int mi = 0; mi < 2; mi++) {
        #pragma unroll
        for (int i = 0; i < 4; i++) {
            int ml = mi * 64 + ty4 + i;
            int m = m0 + ml;
            if (m >= cnt) continue;
            int ga = base + m;
            #pragma unroll
            for (int ni = 0; ni < 2; ni++) {
                #pragma unroll
                for (int jp = 0; jp < 2; jp++) {
                    int col = n0 + ni * 64 + tx4 + jp * 2;
                    float v0, v1;
                    upk2(acc[mi][ni][i][jp], v0, v1);
                    if (EPI == 0) {
                        if (col < NPad) {
                            float2 v;
                            v.x = (col < NReal) ? v0 : 0.0f;
                            v.y = (col + 1 < NReal) ? v1 : 0.0f;
                            *reinterpret_cast<float2*>(C + (size_t)ga * ldc + col) = v;
                        }
                    } else if (EPI == 2) {
                        float2* cp = reinterpret_cast<float2*>(C + (size_t)ga * ldc + col);
                        float2 v = *cp;
                        v.x += v0; v.y += v1;
                        *cp = v;
                    } else {
                        int tok = g_tok[ga];
                        float wgt = g_w[ga];
                        float* orow = outp + (size_t)tok * HD;
                        atomicAdd(&orow[col], wgt * v0);
                        atomicAdd(&orow[col + 1], wgt * v1);
                    }
                }
            }
        }
    }
}

// ----------------------------------------------------------------------------
// kernel_launch
// Inputs: hidden_states, gate_w, W1, W2, W3, U1, V1, U2, V2, U3, V3
// Output: [out (T*H f32)] then [router_logits (T*E f32)]
// ----------------------------------------------------------------------------
extern "C" void kernel_launch(void* const* d_in, const int* in_sizes, int n_in,
                              void* d_out, int out_size) {
    const float* x  = (const float*)d_in[0];
    const float* gw = (const float*)d_in[1];
    const float* W1 = (const float*)d_in[2];
    const float* W2 = (const float*)d_in[3];
    const float* W3 = (const float*)d_in[4];
    const float* U1 = (const float*)d_in[5];
    const float* V1 = (const float*)d_in[6];
    const float* U2 = (const float*)d_in[7];
    const float* V2 = (const float*)d_in[8];
    const float* U3 = (const float*)d_in[9];
    const float* V3 = (const float*)d_in[10];
    (void)n_in; (void)out_size;

    const int T = in_sizes[0] / HD;
    const int A = T * 2;

    float* out    = (float*)d_out;
    float* logits = out + (size_t)T * HD;

    zero_kernel<<<2048, 256>>>(out, (size_t)T * HD);
    router_kernel<<<T, 256>>>(x, gw, logits);
    scan_kernel<<<1, 1>>>();
    scatter_kernel<<<(T + 255) / 256, 256>>>(T);

    // zero-padded low-rank U matrices (fp32, exact)
    pad_kernel<<<2048, 256>>>(U1, g_U1p, NE * FD);
    pad_kernel<<<2048, 256>>>(U3, g_U3p, NE * FD);
    pad_kernel<<<1024, 256>>>(U2, g_U2p, NE * HD);

    const int mt128 = (T + 127) / 128;

    // P1 = X@V1^T, P3 = X@V3^T  (N=79 -> stride 96 zero-padded)
    {
        dim3 grid(1, mt128, NE);
        gemm_f2<HD, true, 0><<<grid, 256>>>(
            x, V1, (size_t)RD * HD, RD, g_P1, RP, RD, RP, nullptr);
        gemm_f2<HD, true, 0><<<grid, 256>>>(
            x, V3, (size_t)RD * HD, RD, g_P3, RP, RD, RP, nullptr);
    }
    // gate = X@W1^T, up = X@W3^T
    {
        dim3 grid(FD / 128, mt128, NE);
        gemm_f2<HD, true, 0><<<grid, 256>>>(
            x, W1, (size_t)FD * HD, FD, g_gate, FD, FD, FD, nullptr);
        gemm_f2<HD, true, 0><<<grid, 256>>>(
            x, W3, (size_t)FD * HD, FD, g_up, FD, FD, FD, nullptr);
    }
    // gate += P1@U1p^T, up += P3@U3p^T  (K=96)
    {
        dim3 grid(FD / 128, mt128, NE);
        gemm_f2<RP, false, 2><<<grid, 256>>>(
            g_P1, g_U1p, (size_t)FD * RP, FD, g_gate, FD, FD, FD, nullptr);
        gemm_f2<RP, false, 2><<<grid, 256>>>(
            g_P3, g_U3p, (size_t)FD * RP, FD, g_up, FD, FD, FD, nullptr);
    }
    // Hact = silu(gate)*up
    silu_mul_kernel<<<4096, 256>>>(g_gate, g_up, (size_t)A * FD);

    // Q2 = Hact@V2^T  (K=3584, N=79 -> stride 96)
    {
        dim3 grid(1, mt128, NE);
        gemm_f2<FD, false, 0><<<grid, 256>>>(
            g_gate, V2, (size_t)RD * FD, RD, g_Q2, RP, RD, RP, nullptr);
    }
    // out += w*(Hact@W2^T)  (K=3584, atomic scatter)
    {
        dim3 grid(HD / 128, mt128, NE);
        gemm_f2<FD, false, 3><<<grid, 256>>>(
            g_gate, W2, (size_t)HD * FD, HD, nullptr, HD, HD, HD, out);
    }
    // out += w*(Q2@U2p^T)  (K=96, atomic scatter)
    {
        dim3 grid(HD / 128, mt128, NE);
        gemm_f2<RP, false, 3><<<grid, 256>>>(
            g_Q2, g_U2p, (size_t)HD * RP, HD, nullptr, HD, HD, HD, out);
    }
}